// round 9
// baseline (speedup 1.0000x reference)
#include <cuda_runtime.h>
#include <cstdint>

#define B_  512
#define C_  6
#define T_  77
#define D_  512
#define LI_ 193

#define OFF_GT 0
#define OFF_GI (B_ * D_)
#define OFF_LT (2 * B_ * D_)
#define OFF_LS (2 * B_ * D_ + B_ * C_ * D_)

#define CHUNK  8          // rows per pipeline stage
#define NBUF   3          // smem ring depth
#define NCHUNK 10         // ceil(77/8); last chunk has 5 rows

#define CP_ASYNC16(saddr, gptr) \
    asm volatile("cp.async.cg.shared.global [%0], [%1], 16;" \
                 :: "r"(saddr), "l"(gptr))
#define CP_COMMIT() asm volatile("cp.async.commit_group;" ::: "memory")
#define CP_WAIT(n)  asm volatile("cp.async.wait_group %0;" :: "n"(n) : "memory")

// Grid = B*2: CTA (b,h) owns d-range [h*256,(h+1)*256). 64 threads, one float4
// column each. Rows stream through a 3-deep cp.async smem ring; each thread
// copies and consumes only its own 16B lane -> no barriers in the main loop.
__global__ __launch_bounds__(64, 8)
void clip_fused_kernel(const float* __restrict__ image_features,   // [B, LI, D]
                       const float* __restrict__ text_features,    // [B, T, D]
                       const float* __restrict__ logit_scale,      // [1]
                       const int*   __restrict__ captions,         // [B, T]
                       const int*   __restrict__ noun_chunk_mask,  // [B, C, T]
                       float* __restrict__ out)
{
    const int b   = blockIdx.x >> 1;
    const int h   = blockIdx.x & 1;
    const int tid = threadIdx.x;           // 0..63 -> float4 col within D-half

    __shared__ float4 s_buf[NBUF][CHUNK][64];
    __shared__ int    s_mask[T_];
    __shared__ int    s_val[T_];
    __shared__ int    s_eot;

    // ---- Stage packed noun_chunk_mask + caption values ----
    for (int t = tid; t < T_; t += 64) {
        int pack = 0;
        const int* mrow = noun_chunk_mask + (size_t)b * C_ * T_ + t;
        #pragma unroll
        for (int c = 0; c < C_; ++c)
            if (mrow[c * T_] != 0) pack |= (1 << c);
        s_mask[t] = pack;
        s_val[t]  = captions[(size_t)b * T_ + t];
    }

    // global_image slice (independent traffic, issue early)
    {
        const float4* img4 = reinterpret_cast<const float4*>(
            image_features + (size_t)b * LI_ * D_) + h * 64;
        float4 gi = img4[tid];
        reinterpret_cast<float4*>(out + OFF_GI + (size_t)b * D_)[h * 64 + tid] = gi;
    }

    const float4* trow = reinterpret_cast<const float4*>(
        text_features + (size_t)b * T_ * D_) + h * 64 + tid;   // stride D/4

    // per-thread smem lane base (byte address in shared window)
    uint32_t s_lane;
    {
        const void* p = &s_buf[0][0][tid];
        asm("{ .reg .u64 t; cvta.to.shared.u64 t, %1; cvt.u32.u64 %0, t; }"
            : "=r"(s_lane) : "l"(p));
    }
    const uint32_t BUFB = CHUNK * 64 * 16;   // bytes per buffer
    const uint32_t ROWB = 64 * 16;           // bytes per row

    // ---- Prologue: issue chunks 0 and 1 ----
    #pragma unroll
    for (int k = 0; k < 2; ++k) {
        const int t0  = k * CHUNK;
        const int len = CHUNK;               // chunks 0,1 are full
        const uint32_t sb = s_lane + (uint32_t)k * BUFB;
        #pragma unroll
        for (int r = 0; r < CHUNK; ++r) {
            if (r < len)
                CP_ASYNC16(sb + r * ROWB, trow + (t0 + r) * (D_ / 4));
        }
        CP_COMMIT();
    }

    __syncthreads();   // masks staged (buffers are per-thread; no sync needed for them)

    float4 acc[C_];
    #pragma unroll
    for (int c = 0; c < C_; ++c) acc[c] = make_float4(0.f, 0.f, 0.f, 0.f);

    // ---- Main pipeline ----
    for (int k = 0; k < NCHUNK; ++k) {
        if (k == NCHUNK - 1) { CP_WAIT(0); } else { CP_WAIT(1); }

        const int buf = k % NBUF;
        const int t0  = k * CHUNK;
        const int len = (k == NCHUNK - 1) ? (T_ - t0) : CHUNK;

        #pragma unroll
        for (int r = 0; r < CHUNK; ++r) {
            if (r < len) {
                float4 x = s_buf[buf][r][tid];
                const int pack = s_mask[t0 + r];
                #pragma unroll
                for (int c = 0; c < C_; ++c) {
                    if (pack & (1 << c)) {
                        acc[c].x += x.x; acc[c].y += x.y;
                        acc[c].z += x.z; acc[c].w += x.w;
                    }
                }
            }
        }

        const int kn = k + 2;
        if (kn < NCHUNK) {
            const int nt0  = kn * CHUNK;
            const int nlen = (kn == NCHUNK - 1) ? (T_ - nt0) : CHUNK;
            const uint32_t sb = s_lane + (uint32_t)(kn % NBUF) * BUFB;
            #pragma unroll
            for (int r = 0; r < CHUNK; ++r) {
                if (r < nlen)
                    CP_ASYNC16(sb + r * ROWB, trow + (nt0 + r) * (D_ / 4));
            }
            CP_COMMIT();
        }
    }

    // ---- Warp 0: argmax over captions (first occurrence on ties) ----
    if (tid < 32) {
        int v = s_val[tid];
        int i = tid;
        #pragma unroll
        for (int k = 32; k < 96; k += 32) {
            int t = tid + k;
            if (t < T_) {
                int v2 = s_val[t];
                if (v2 > v) { v = v2; i = t; }
            }
        }
        #pragma unroll
        for (int off = 16; off > 0; off >>= 1) {
            int v2 = __shfl_xor_sync(0xFFFFFFFFu, v, off);
            int i2 = __shfl_xor_sync(0xFFFFFFFFu, i, off);
            if (v2 > v || (v2 == v && i2 < i)) { v = v2; i = i2; }
        }
        if (tid == 0) s_eot = i;
    }

    // ---- Write local_text for all 6 channels (this D-half) ----
    const float inv_T = 1.0f / (float)T_;
    float4* lt = reinterpret_cast<float4*>(out + OFF_LT + (size_t)b * C_ * D_)
                 + h * 64 + tid;
    #pragma unroll
    for (int c = 0; c < C_; ++c) {
        float4 r;
        r.x = acc[c].x * inv_T; r.y = acc[c].y * inv_T;
        r.z = acc[c].z * inv_T; r.w = acc[c].w * inv_T;
        lt[c * (D_ / 4)] = r;
    }

    __syncthreads();   // s_eot visible

    // global_text slice: gather eot row (L1/L2 hot)
    {
        float4 g = trow[s_eot * (D_ / 4)];
        reinterpret_cast<float4*>(out + OFF_GT + (size_t)b * D_)[h * 64 + tid] = g;
    }

    if (blockIdx.x == 0 && tid == 0) {
        out[OFF_LS] = logit_scale[0];
    }
}

extern "C" void kernel_launch(void* const* d_in, const int* in_sizes, int n_in,
                              void* d_out, int out_size)
{
    const float* image_features  = (const float*)d_in[0];
    const float* text_features   = (const float*)d_in[1];
    const float* logit_scale     = (const float*)d_in[2];
    const int*   captions        = (const int*)d_in[3];
    const int*   noun_chunk_mask = (const int*)d_in[4];
    float* out = (float*)d_out;

    clip_fused_kernel<<<B_ * 2, 64>>>(image_features, text_features, logit_scale,
                                      captions, noun_chunk_mask, out);
}